// round 7
// baseline (speedup 1.0000x reference)
#include <cuda_runtime.h>
#include <cuda_fp16.h>
#include <math.h>

// KDLayerNorm: per-row kernel-density CDF -> Gaussian PPF normalization.
// 2*cdf_i - 1 = (1/D) * sum_j erf((x_i-x_j)/(bw*sqrt2))
// erf(t) ~= tanh(t * q(min(t^2,12.25))), q quadratic; scalar f32 + MUFU tanh.
// Antisymmetric exchange, TWO ROWS PER THREAD (t, t+128); exchanged pair
// travels as one f16x2 word and is accumulated with HADD2 (per-4 flush to f32).

#define D 256
#define H 128              // threads per block
#define CW 16              // offsets per exchange chunk
#define NCH 8              // chunks cover d = 0..127

__device__ __forceinline__ float tanh_fast(float x) {
    float y; asm("tanh.approx.f32 %0, %1;" : "=f"(y) : "f"(x)); return y;
}

// atanh(erf(x))/x quadratic-in-x^2 fit (interp at s=0, 2.25, 9; s clamped at 12.25)
#define QC0 1.1283792f
#define QC1 0.104728f
#define QC2 (-0.00208245f)
#define SMAX 12.25f

__global__ __launch_bounds__(H, 12)
void kdln_kernel(const float* __restrict__ x,
                 const float* __restrict__ weight,
                 const float* __restrict__ bias,
                 float* __restrict__ out)
{
    __shared__ float2 sxw[D];                 // word i = {-xs_i, -xs_((i+128)%256)} (2KB)
    __shared__ unsigned int sfh[CW][H];       // exchange: f16x2 {f_d(j), f_d(j+128)} (8KB)
    __shared__ float wsum[4], wsq[4];

    const int row = blockIdx.x;
    const int t   = threadIdx.x;

    const float v0 = x[row * D + t];
    const float v1 = x[row * D + t + H];

    // --- row mean / var (ddof=1) over 256 values, 2 per thread ---
    float s = v0 + v1, s2 = v0 * v0 + v1 * v1;
    #pragma unroll
    for (int o = 16; o > 0; o >>= 1) {
        s  += __shfl_xor_sync(0xFFFFFFFFu, s,  o);
        s2 += __shfl_xor_sync(0xFFFFFFFFu, s2, o);
    }
    if ((t & 31) == 0) { wsum[t >> 5] = s; wsq[t >> 5] = s2; }
    __syncthreads();

    float S = 0.f, S2 = 0.f;
    #pragma unroll
    for (int i = 0; i < 4; i++) { S += wsum[i]; S2 += wsq[i]; }

    const float mean = S * (1.0f / D);
    const float var  = (S2 - (float)D * mean * mean) * (1.0f / (D - 1));
    // 0.9 * 256^(-0.2) = 0.2968892799239037
    const float bw   = 0.2968892799239037f * sqrtf(var);
    const float inv  = 1.0f / (bw * 1.4142135623730951f);  // 1/(bw*sqrt2)

    const float m0 = v0 * inv;
    const float m1 = v1 * inv;
    sxw[t]     = make_float2(-m0, -m1);   // word t:     {-xs_t,       -xs_(t+128)}
    sxw[t + H] = make_float2(-m1, -m0);   // word t+128: {-xs_(t+128), -xs_t}
    __syncthreads();

    float accP0 = 0.f, accP1 = 0.f;   // direct terms (rows t / t+128)
    float accM0 = 0.f, accM1 = 0.f;   // exchanged terms

    for (int c = 0; c < NCH; c++) {
        const int dbase = c * CW;

        // --- compute phase: scalar erf for both rows at offsets d = dbase..dbase+15 ---
        #pragma unroll
        for (int u = 0; u < CW; u++) {
            const int d = dbase + u;
            const float2 y = sxw[t + d];       // {-xs_(t+d), -xs_((t+d+128)%256)}
            const float t0 = m0 + y.x;
            const float t1 = m1 + y.y;
            const float s0 = fminf(t0 * t0, SMAX);
            const float s1 = fminf(t1 * t1, SMAX);
            float q0 = fmaf(s0, QC2, QC1); q0 = fmaf(q0, s0, QC0);
            float q1 = fmaf(s1, QC2, QC1); q1 = fmaf(q1, s1, QC0);
            const float e0 = tanh_fast(q0 * t0);
            const float e1 = tanh_fast(q1 * t1);
            const __half2 hh = __floats2half2_rn(e0, e1);
            sfh[u][t] = *(const unsigned int*)&hh;
            accP0 += e0;
            accP1 += e1;
        }
        __syncthreads();

        // --- exchange phase: row r picks up -f_d((r-d) mod 256); HADD2, per-4 flush ---
        #pragma unroll
        for (int u4 = 0; u4 < CW / 4; u4++) {
            __half2 hacc = __float2half2_rn(0.0f);
            #pragma unroll
            for (int w = 0; w < 4; w++) {
                const int u = u4 * 4 + w;
                const int d = dbase + u;
                unsigned int g = sfh[u][(t - d) & (H - 1)];
                if (t < d) g = __byte_perm(g, 0, 0x1032);   // swap halves on wrap
                hacc = __hadd2(hacc, *(const __half2*)&g);
            }
            const float2 gf = __half22float2(hacc);
            accM0 += gf.x;
            accM1 += gf.y;
        }
        __syncthreads();   // sfh reused next chunk
    }

    // --- d = 128: self-dual within the thread (rows t and t+128 are partners) ---
    const float t128 = m0 - m1;
    const float s128 = fminf(t128 * t128, SMAX);
    const float p128 = fmaf(fmaf(QC2, s128, QC1), s128, QC0) * t128;
    const float e128 = tanh_fast(p128);

    const float acc_lo = accP0 - accM0 + e128;
    const float acc_hi = accP1 - accM1 - e128;

    // 2*cdf - 1 = acc / D
    const float n0 = erfinvf(acc_lo * (1.0f / D)) * 1.4142135623730951f;
    const float n1 = erfinvf(acc_hi * (1.0f / D)) * 1.4142135623730951f;
    out[row * D + t]     = n0 * weight[t]     + bias[t];
    out[row * D + t + H] = n1 * weight[t + H] + bias[t + H];
}

extern "C" void kernel_launch(void* const* d_in, const int* in_sizes, int n_in,
                              void* d_out, int out_size)
{
    const float* x = (const float*)d_in[0];
    const float* w = (const float*)d_in[1];
    const float* b = (const float*)d_in[2];
    float* out = (float*)d_out;

    const int n_rows = in_sizes[0] / D;   // 4096
    kdln_kernel<<<n_rows, H>>>(x, w, b, out);
}

// round 10
// speedup vs baseline: 1.0569x; 1.0569x over previous
#include <cuda_runtime.h>
#include <cuda_fp16.h>
#include <math.h>

// KDLayerNorm: per-row kernel-density CDF -> Gaussian PPF normalization.
// 2*cdf_i - 1 = (1/D) * sum_j erf((x_i-x_j)/(bw*sqrt2))
// erf(t) ~= tanh(t * q(min(t^2,12.25))), q quadratic, evaluated in f16x2
// (both rows of the thread in one packed lane) with tanh.approx.f16x2.
// Antisymmetric exchange: TWO ROWS PER THREAD (t, t+128); exchanged pair is
// the f16x2 tanh result word; HADD2 accumulation with per-4 f32 flush.

#define D 256
#define H 128              // threads per block
#define CW 16              // offsets per exchange chunk
#define NCH 8              // chunks cover d = 0..127

__device__ __forceinline__ float kdln_tanhf(float x) {
    float y; asm("tanh.approx.f32 %0, %1;" : "=f"(y) : "f"(x)); return y;
}
__device__ __forceinline__ __half2 kdln_tanh2(__half2 x) {
    unsigned int xi = *(unsigned int*)&x, ri;
    asm("tanh.approx.f16x2 %0, %1;" : "=r"(ri) : "r"(xi));
    return *(__half2*)&ri;
}

// atanh(erf(x))/x quadratic-in-x^2 fit (interp at s=0, 2.25, 9; s clamped at 12.25)
#define QC0 1.1283792f
#define QC1 0.104728f
#define QC2 (-0.00208245f)
#define SMAX 12.25f

__global__ __launch_bounds__(H, 12)
void kdln_kernel(const float* __restrict__ x,
                 const float* __restrict__ weight,
                 const float* __restrict__ bias,
                 float* __restrict__ out)
{
    __shared__ float2 sxw[D];                 // word i = {-xs_i, -xs_((i+128)%256)} (2KB)
    __shared__ unsigned int sfh[CW][H];       // exchange: f16x2 {f_d(j), f_d(j+128)} (8KB)
    __shared__ float wsum[4], wsq[4];

    const int row = blockIdx.x;
    const int t   = threadIdx.x;

    const float v0 = x[row * D + t];
    const float v1 = x[row * D + t + H];

    // --- row mean / var (ddof=1) over 256 values, 2 per thread ---
    float s = v0 + v1, s2 = v0 * v0 + v1 * v1;
    #pragma unroll
    for (int o = 16; o > 0; o >>= 1) {
        s  += __shfl_xor_sync(0xFFFFFFFFu, s,  o);
        s2 += __shfl_xor_sync(0xFFFFFFFFu, s2, o);
    }
    if ((t & 31) == 0) { wsum[t >> 5] = s; wsq[t >> 5] = s2; }
    __syncthreads();

    float S = 0.f, S2 = 0.f;
    #pragma unroll
    for (int i = 0; i < 4; i++) { S += wsum[i]; S2 += wsq[i]; }

    const float mean = S * (1.0f / D);
    const float var  = (S2 - (float)D * mean * mean) * (1.0f / (D - 1));
    // 0.9 * 256^(-0.2) = 0.2968892799239037
    const float bw   = 0.2968892799239037f * sqrtf(var);
    const float inv  = 1.0f / (bw * 1.4142135623730951f);  // 1/(bw*sqrt2)

    const float m0 = v0 * inv;
    const float m1 = v1 * inv;
    sxw[t]     = make_float2(-m0, -m1);   // word t:     {-xs_t,       -xs_(t+128)}
    sxw[t + H] = make_float2(-m1, -m0);   // word t+128: {-xs_(t+128), -xs_t}
    __syncthreads();

    const __half2 C0h = __float2half2_rn(QC0);
    const __half2 C1h = __float2half2_rn(QC1);
    const __half2 C2h = __float2half2_rn(QC2);
    const __half2 SMX = __float2half2_rn(SMAX);

    float accP0 = 0.f, accP1 = 0.f;   // direct terms (rows t / t+128)
    float accM0 = 0.f, accM1 = 0.f;   // exchanged terms

    for (int c = 0; c < NCH; c++) {
        const int dbase = c * CW;

        // --- compute phase: f16x2 erf for both rows, offsets d = dbase..dbase+15 ---
        #pragma unroll
        for (int u4 = 0; u4 < CW / 4; u4++) {
            __half2 pacc = __float2half2_rn(0.0f);
            #pragma unroll
            for (int w = 0; w < 4; w++) {
                const int u = u4 * 4 + w;
                const int d = dbase + u;
                const float2 y = sxw[t + d];       // {-xs_(t+d), -xs_((t+d+128)%256)}
                const float t0 = m0 + y.x;          // f32: avoid f16 cancellation bias
                const float t1 = m1 + y.y;
                const __half2 th = __floats2half2_rn(t0, t1);
                __half2 sq = __hmul2(th, th);
                sq = __hmin2(sq, SMX);
                __half2 q = __hfma2(sq, C2h, C1h);
                q = __hfma2(q, sq, C0h);
                const __half2 e = kdln_tanh2(__hmul2(q, th));
                sfh[u][t] = *(const unsigned int*)&e;
                pacc = __hadd2(pacc, e);
            }
            const float2 pf = __half22float2(pacc);
            accP0 += pf.x;
            accP1 += pf.y;
        }
        __syncthreads();

        // --- exchange phase: row r picks up -f_d((r-d) mod 256); HADD2, per-4 flush ---
        #pragma unroll
        for (int u4 = 0; u4 < CW / 4; u4++) {
            __half2 hacc = __float2half2_rn(0.0f);
            #pragma unroll
            for (int w = 0; w < 4; w++) {
                const int u = u4 * 4 + w;
                const int d = dbase + u;
                unsigned int g = sfh[u][(t - d) & (H - 1)];
                if (t < d) g = __byte_perm(g, 0, 0x1032);   // swap halves on wrap
                hacc = __hadd2(hacc, *(const __half2*)&g);
            }
            const float2 gf = __half22float2(hacc);
            accM0 += gf.x;
            accM1 += gf.y;
        }
        __syncthreads();   // sfh reused next chunk
    }

    // --- d = 128: self-dual within the thread (rows t and t+128 are partners) ---
    const float t128 = m0 - m1;
    const float s128 = fminf(t128 * t128, SMAX);
    const float p128 = fmaf(fmaf(QC2, s128, QC1), s128, QC0) * t128;
    const float e128 = kdln_tanhf(p128);

    const float acc_lo = accP0 - accM0 + e128;
    const float acc_hi = accP1 - accM1 - e128;

    // 2*cdf - 1 = acc / D
    const float n0 = erfinvf(acc_lo * (1.0f / D)) * 1.4142135623730951f;
    const float n1 = erfinvf(acc_hi * (1.0f / D)) * 1.4142135623730951f;
    out[row * D + t]     = n0 * weight[t]     + bias[t];
    out[row * D + t + H] = n1 * weight[t + H] + bias[t + H];
}

extern "C" void kernel_launch(void* const* d_in, const int* in_sizes, int n_in,
                              void* d_out, int out_size)
{
    const float* x = (const float*)d_in[0];
    const float* w = (const float*)d_in[1];
    const float* b = (const float*)d_in[2];
    float* out = (float*)d_out;

    const int n_rows = in_sizes[0] / D;   // 4096
    kdln_kernel<<<n_rows, H>>>(x, w, b, out);
}

// round 11
// speedup vs baseline: 1.1401x; 1.0786x over previous
#include <cuda_runtime.h>
#include <cuda_fp16.h>
#include <math.h>

// KDLayerNorm: per-row kernel-density CDF -> Gaussian PPF normalization.
// 2*cdf_i - 1 = (1/D) * sum_j erf((x_i-x_j)/(bw*sqrt2))
// erf(t) ~= tanh(t * q(min(t^2,12.25))), q quadratic, f16x2 + tanh.approx.f16x2.
// TWO DATA ROWS PER CTA (256 threads): f16x2 lanes = {row A, row B} at same
// column. Antisymmetric exchange is a pure shift mod 256 -> no half-swap.
// Wrap-free via duplicated shared regions (no ISETP/PRMT/AND in hot loop).

#define DD 256
#define TB 256             // threads per block (one column each, 2 rows)
#define CW 16              // offsets per exchange chunk
#define NCH 8              // chunks cover d = 0..127 (d=0 contributes zeros)

__device__ __forceinline__ float kdln_tanhf(float x) {
    float y; asm("tanh.approx.f32 %0, %1;" : "=f"(y) : "f"(x)); return y;
}
__device__ __forceinline__ __half2 kdln_tanh2(__half2 x) {
    unsigned int xi = *(unsigned int*)&x, ri;
    asm("tanh.approx.f16x2 %0, %1;" : "=r"(ri) : "r"(xi));
    return *(__half2*)&ri;
}
typedef unsigned long long u64;
__device__ __forceinline__ u64 kdln_add2(u64 a, u64 b) {
    u64 r; asm("add.rn.f32x2 %0, %1, %2;" : "=l"(r) : "l"(a), "l"(b)); return r;
}
__device__ __forceinline__ u64 kdln_pack2(float lo, float hi) {
    u64 r; asm("mov.b64 %0, {%1, %2};" : "=l"(r) : "f"(lo), "f"(hi)); return r;
}
__device__ __forceinline__ void kdln_unpack2(u64 v, float& lo, float& hi) {
    asm("mov.b64 {%0, %1}, %2;" : "=f"(lo), "=f"(hi) : "l"(v));
}

// atanh(erf(x))/x quadratic-in-x^2 fit (interp at s=0, 2.25, 9; s clamped at 12.25)
#define QC0 1.1283792f
#define QC1 0.104728f
#define QC2 (-0.00208245f)
#define SMAX 12.25f

__global__ __launch_bounds__(TB, 8)
void kdln_kernel(const float* __restrict__ x,
                 const float* __restrict__ weight,
                 const float* __restrict__ bias,
                 float* __restrict__ out)
{
    __shared__ u64 syw[DD + 128];              // word k = {-xsA_k, -xsB_k}, wrap-extended (3KB)
    __shared__ unsigned int sfh[CW][DD + 128]; // exchange f16x2 {eA,eB}; [u][k+128], dup for k>=128 (24KB)
    __shared__ float red[8][4];

    const int rowA = blockIdx.x * 2;
    const int t    = threadIdx.x;

    const float vA = x[rowA * DD + t];
    const float vB = x[rowA * DD + DD + t];

    // --- per-row mean / var (ddof=1), both rows at once ---
    float sA = vA, qA = vA * vA, sB = vB, qB = vB * vB;
    #pragma unroll
    for (int o = 16; o > 0; o >>= 1) {
        sA += __shfl_xor_sync(0xFFFFFFFFu, sA, o);
        qA += __shfl_xor_sync(0xFFFFFFFFu, qA, o);
        sB += __shfl_xor_sync(0xFFFFFFFFu, sB, o);
        qB += __shfl_xor_sync(0xFFFFFFFFu, qB, o);
    }
    if ((t & 31) == 0) {
        red[t >> 5][0] = sA; red[t >> 5][1] = qA;
        red[t >> 5][2] = sB; red[t >> 5][3] = qB;
    }
    __syncthreads();

    float SA = 0.f, QA = 0.f, SB = 0.f, QB = 0.f;
    #pragma unroll
    for (int i = 0; i < 8; i++) {
        SA += red[i][0]; QA += red[i][1];
        SB += red[i][2]; QB += red[i][3];
    }

    const float meanA = SA * (1.0f / DD);
    const float meanB = SB * (1.0f / DD);
    const float varA  = (QA - (float)DD * meanA * meanA) * (1.0f / (DD - 1));
    const float varB  = (QB - (float)DD * meanB * meanB) * (1.0f / (DD - 1));
    // 1 / (0.9 * 256^(-0.2) * sqrt(2)) = 1 / 0.419865...
    const float invA = 1.0f / (0.419866213371f * sqrtf(varA));
    const float invB = 1.0f / (0.419866213371f * sqrtf(varB));

    const float mA = vA * invA;
    const float mB = vB * invB;
    const u64 negm = kdln_pack2(-mA, -mB);
    syw[t] = negm;
    if (t < 128) syw[t + DD] = negm;           // wrap extension for direct phase
    __syncthreads();

    const u64 my2 = kdln_pack2(mA, mB);
    const __half2 C0h = __float2half2_rn(QC0);
    const __half2 C1h = __float2half2_rn(QC1);
    const __half2 C2h = __float2half2_rn(QC2);
    const __half2 SMX = __float2half2_rn(SMAX);

    float accPA = 0.f, accPB = 0.f;   // direct terms  (j = t+1 .. t+127, +d=0 zero)
    float accMA = 0.f, accMB = 0.f;   // exchanged terms (j = t-1 .. t-127)

    for (int c = 0; c < NCH; c++) {
        const int dbase = c * CW;

        // --- compute phase: f16x2 erf {rowA,rowB} at offsets d = dbase..dbase+15 ---
        #pragma unroll
        for (int u4 = 0; u4 < CW / 4; u4++) {
            __half2 pacc = __float2half2_rn(0.0f);
            #pragma unroll
            for (int w = 0; w < 4; w++) {
                const int u = u4 * 4 + w;
                const int d = dbase + u;
                const u64 t2 = kdln_add2(my2, syw[t + d]);   // f32: no cancellation bias
                float t0, t1; kdln_unpack2(t2, t0, t1);
                const __half2 th = __floats2half2_rn(t0, t1);
                __half2 sq = __hmul2(th, th);
                sq = __hmin2(sq, SMX);
                __half2 q = __hfma2(sq, C2h, C1h);
                q = __hfma2(q, sq, C0h);
                const __half2 e = kdln_tanh2(__hmul2(q, th));
                const unsigned int ew = *(const unsigned int*)&e;
                sfh[u][t + 128] = ew;
                if (t >= 128) sfh[u][t - 128] = ew;          // warp-uniform duplicate
                pacc = __hadd2(pacc, e);
            }
            const float2 pf = __half22float2(pacc);
            accPA += pf.x;
            accPB += pf.y;
        }
        __syncthreads();

        // --- exchange phase: -f_d((t-d) mod 256) = -sfh[u][t-d+128]; no swap needed ---
        #pragma unroll
        for (int u4 = 0; u4 < CW / 4; u4++) {
            __half2 hacc = __float2half2_rn(0.0f);
            #pragma unroll
            for (int w = 0; w < 4; w++) {
                const int u = u4 * 4 + w;
                const unsigned int g = sfh[u][t - dbase - u + 128];
                hacc = __hadd2(hacc, *(const __half2*)&g);
            }
            const float2 gf = __half22float2(hacc);
            accMA += gf.x;
            accMB += gf.y;
        }
        __syncthreads();   // sfh reused next chunk
    }

    // --- d = 128 term: direct only (j = t+128; its mirror j = t-128 is the same j) ---
    float y128A, y128B;
    kdln_unpack2(syw[t + 128], y128A, y128B);  // {-xsA_{t+128}, -xsB_{t+128}} (mod 256 via dup)
    const float tA = mA + y128A;
    const float tB = mB + y128B;
    const float sA2 = fminf(tA * tA, SMAX);
    const float sB2 = fminf(tB * tB, SMAX);
    const float eA = kdln_tanhf(fmaf(fmaf(QC2, sA2, QC1), sA2, QC0) * tA);
    const float eB = kdln_tanhf(fmaf(fmaf(QC2, sB2, QC1), sB2, QC0) * tB);

    const float accA = accPA - accMA + eA;
    const float accB = accPB - accMB + eB;

    // 2*cdf - 1 = acc / D
    const float nA = erfinvf(accA * (1.0f / DD)) * 1.4142135623730951f;
    const float nB = erfinvf(accB * (1.0f / DD)) * 1.4142135623730951f;
    const float wt = weight[t];
    const float bs = bias[t];
    out[rowA * DD + t]      = nA * wt + bs;
    out[rowA * DD + DD + t] = nB * wt + bs;
}

extern "C" void kernel_launch(void* const* d_in, const int* in_sizes, int n_in,
                              void* d_out, int out_size)
{
    const float* x = (const float*)d_in[0];
    const float* w = (const float*)d_in[1];
    const float* b = (const float*)d_in[2];
    float* out = (float*)d_out;

    const int n_rows = in_sizes[0] / DD;   // 4096
    kdln_kernel<<<n_rows / 2, TB>>>(x, w, b, out);
}